// round 12
// baseline (speedup 1.0000x reference)
#include <cuda_runtime.h>
#include <math.h>

// ---------------- constants ----------------
#define L 256
#define C 384
#define NH 12
#define MLPD 1536
#define NB 12
#define NCTA 296
#define NGRP 8
#define GRPSZ 37
#define INV_S 0.99999500003749968f
#define GEMM_SMEM (4 * 64 * 36 * 4)           // one operand, 4 stages
#define MEGA_SMEM (2 * GEMM_SMEM)             // 73728 bytes

// ---------------- scratch ----------------
__device__ __align__(16) float g_t[L * C];
__device__ __align__(16) float g_y[L * C];
__device__ __align__(16) float g_att[L * C];
__device__ __align__(16) float g_z[L * C];
__device__ __align__(16) float g_h1[L * MLPD];         // gelu(fc1) output
__device__ __align__(16) float g_qkvp[4 * L * 3 * C];  // qkv split-K partials (S=4)
__device__ __align__(16) float g_part[12 * L * C];     // generic split-K partials (S<=12)
__device__ __align__(16) float g_col[L * 768];
__device__ __align__(16) float g_d1[3 * 256 * 256];
__device__ __align__(16) float g_skip[4 * 256];

// ---------------- global barrier (tree arrival, one-hop publish) ----------------
__device__ unsigned g_cnt[NGRP * 32];   // one counter per 128B line
__device__ unsigned g_root;
__device__ volatile unsigned g_gen;

__global__ void reset_kernel() {
    int t = threadIdx.x;
    if (t < NGRP * 32) g_cnt[t] = 0;
    if (t == 0) { g_root = 0; g_gen = 0; }
    __threadfence();
}

__device__ __forceinline__ void gsync() {
    __syncthreads();
    if (threadIdx.x == 0) {
        __threadfence();
        unsigned gen = g_gen;
        int grp = (blockIdx.x & 7) * 32;
        if (atomicAdd(&g_cnt[grp], 1u) == GRPSZ - 1) {
            g_cnt[grp] = 0;
            if (atomicAdd(&g_root, 1u) == NGRP - 1) {
                g_root = 0;
                __threadfence();
                g_gen = gen + 1;           // one-hop publish
            }
        }
        int spins = 0;
        while (g_gen == gen) {             // publisher exits immediately
            if (++spins > 64) __nanosleep(32);
        }
        __threadfence();
    }
    __syncthreads();
}

// ---------------- helpers ----------------
__device__ __forceinline__ void mma_tf32(float c[4], unsigned a0, unsigned a1,
                                         unsigned a2, unsigned a3,
                                         unsigned b0, unsigned b1)
{
    asm volatile(
        "mma.sync.aligned.m16n8k8.row.col.f32.tf32.tf32.f32 "
        "{%0,%1,%2,%3}, {%4,%5,%6,%7}, {%8,%9}, {%0,%1,%2,%3};"
        : "+f"(c[0]), "+f"(c[1]), "+f"(c[2]), "+f"(c[3])
        : "r"(a0), "r"(a1), "r"(a2), "r"(a3), "r"(b0), "r"(b1));
}
__device__ __forceinline__ float gelu_f(float s) {
    return 0.5f * s * (1.0f + erff(s * 0.70710678118654752f));
}
__device__ __forceinline__ void cp16(void* s, const void* g) {
    unsigned sa = (unsigned)__cvta_generic_to_shared(s);
    asm volatile("cp.async.cg.shared.global [%0], [%1], 16;" :: "r"(sa), "l"(g) : "memory");
}
__device__ __forceinline__ void l2pf(const void* g) {
    asm volatile("prefetch.global.L2 [%0];" :: "l"(g));
}
#define CP_COMMIT() asm volatile("cp.async.commit_group;" ::: "memory")
#define CP_WAIT2()  asm volatile("cp.async.wait_group 2;" ::: "memory")

// round-to-nearest tf32: add half-ULP of 10-bit mantissa; HW ignores low 13 bits
__device__ __forceinline__ unsigned rnd_tf(float x) {
    return __float_as_uint(x) + 0x1000u;
}

// ---------------- TF32 GEMM, cp.async 4-stage pipeline ----------------
template<int EPI>
__device__ void gemm_core(const float* __restrict__ A, int lda,
                          const float* __restrict__ Bw, int ldb,
                          const float* __restrict__ bias,
                          float* __restrict__ outp, int N,
                          int bm, int bn, int k0, int nt, char* smbase)
{
    float (*As)[64][36] = (float(*)[64][36])smbase;
    float (*Bs)[64][36] = (float(*)[64][36])(smbase + GEMM_SMEM);
    const int tid = threadIdx.x;
    const int warp = tid >> 5, lane = tid & 31;
    const int wm = warp & 3, wn = warp >> 2;
    const int grp = lane >> 2, tig = lane & 3;
    const int lr = tid >> 2, lc = (tid & 3) * 8;

    float c[4][4];
#pragma unroll
    for (int i = 0; i < 4; i++)
#pragma unroll
        for (int j = 0; j < 4; j++) c[i][j] = 0.f;

    const float* Ap = A + (size_t)(bm + lr) * lda + k0 + lc;
    const float* Bp = Bw + (size_t)(bn + lr) * ldb + k0 + lc;

#pragma unroll
    for (int s = 0; s < 3; s++) {
        if (s < nt) {
            cp16(&As[s][lr][lc],     Ap + s * 32);
            cp16(&As[s][lr][lc + 4], Ap + s * 32 + 4);
            cp16(&Bs[s][lr][lc],     Bp + s * 32);
            cp16(&Bs[s][lr][lc + 4], Bp + s * 32 + 4);
        }
        CP_COMMIT();
    }

    for (int it = 0; it < nt; it++) {
        CP_WAIT2();
        __syncthreads();
        int buf = it & 3;
#pragma unroll
        for (int ks = 0; ks < 4; ks++) {
            int kk = ks * 8;
            unsigned a0 = rnd_tf(As[buf][wm * 16 + grp][kk + tig]);
            unsigned a1 = rnd_tf(As[buf][wm * 16 + grp + 8][kk + tig]);
            unsigned a2 = rnd_tf(As[buf][wm * 16 + grp][kk + tig + 4]);
            unsigned a3 = rnd_tf(As[buf][wm * 16 + grp + 8][kk + tig + 4]);
#pragma unroll
            for (int nb = 0; nb < 4; nb++) {
                unsigned b0 = rnd_tf(Bs[buf][wn * 32 + nb * 8 + grp][kk + tig]);
                unsigned b1 = rnd_tf(Bs[buf][wn * 32 + nb * 8 + grp][kk + tig + 4]);
                mma_tf32(c[nb], a0, a1, a2, a3, b0, b1);
            }
        }
        if (it + 3 < nt) {
            int nbuf = (it + 3) & 3;
            cp16(&As[nbuf][lr][lc],     Ap + (it + 3) * 32);
            cp16(&As[nbuf][lr][lc + 4], Ap + (it + 3) * 32 + 4);
            cp16(&Bs[nbuf][lr][lc],     Bp + (it + 3) * 32);
            cp16(&Bs[nbuf][lr][lc + 4], Bp + (it + 3) * 32 + 4);
        }
        CP_COMMIT();
    }

    int r0 = bm + wm * 16 + grp, r1 = r0 + 8;
#pragma unroll
    for (int nb = 0; nb < 4; nb++) {
        int col = bn + wn * 32 + nb * 8 + tig * 2;
        if (EPI == 0) {
            outp[(size_t)r0 * N + col]     = c[nb][0];
            outp[(size_t)r0 * N + col + 1] = c[nb][1];
            outp[(size_t)r1 * N + col]     = c[nb][2];
            outp[(size_t)r1 * N + col + 1] = c[nb][3];
        } else {
            float b0v = bias[col], b1v = bias[col + 1];
            outp[(size_t)r0 * N + col]     = gelu_f(c[nb][0] + b0v);
            outp[(size_t)r0 * N + col + 1] = gelu_f(c[nb][1] + b1v);
            outp[(size_t)r1 * N + col]     = gelu_f(c[nb][2] + b0v);
            outp[(size_t)r1 * N + col + 1] = gelu_f(c[nb][3] + b1v);
        }
    }
}

__device__ __forceinline__ int region3(int h) { return h < 8 ? 0 : (h < 12 ? 1 : 2); }

// ---------------- parameters ----------------
struct MegaParams {
    const float *x, *patch_w, *patch_b, *pos;
    const float *ln1_w, *ln1_b, *qkv_w, *proj_w, *proj_b, *rpb;
    const float *ln2_w, *ln2_b, *fc1_w, *fc1_b, *fc2_w, *fc2_b;
    const float *skip_w, *skip_b, *dt1_w, *dt1_b, *bn1_w, *bn1_b;
    const float *dt2_w, *dt2_b, *bn2_w, *bn2_b;
    float4* out;
};

// ---------------- the persistent megakernel (2 CTAs/SM) ----------------
__global__ __launch_bounds__(256, 2) void mega(MegaParams P)
{
    extern __shared__ __align__(16) char sm[];
    __shared__ float red[4];
    const int bid = blockIdx.x;
    const int tid = threadIdx.x;

    // P0: im2col
    for (int i = bid * 256 + tid; i < 256 * 768; i += NCTA * 256) {
        int patch = i / 768, r = i % 768;
        int ch = r >> 8, pq = r & 255, pp = pq >> 4, q = pq & 15;
        int h = patch >> 4, w = patch & 15;
        g_col[i] = P.x[ch * 65536 + (h * 16 + pp) * 256 + (w * 16 + q)];
    }
    gsync();

    // P1: patch GEMM (M=256, N=384, K=768, S=12, nt=2)
    if (bid < 288) {
        int s = bid % 12, tile = bid / 12;
        int mt = tile & 3, ntl = tile >> 2;
        gemm_core<0>(g_col, 768, P.patch_w, 768, 0,
                     g_part + (size_t)s * (L * C), C, mt * 64, ntl * 64, s * 64, 2, sm);
    } else {
        for (int i = (bid - 288) * 256 + tid; i < 3 * C * C / 4; i += 8 * 256)
            l2pf(P.qkv_w + i * 4);
    }
    gsync();

    // P2: patch reduce + bias + pos + buggy transpose
    for (int i = bid * 256 + tid; i < L * C; i += NCTA * 256) {
        int m = i / C, n = i % C;
        float v = P.patch_b[n];
#pragma unroll
        for (int s = 0; s < 12; s++) v += g_part[(size_t)s * (L * C) + i];
        int o = n * 256 + m;
        g_t[o] = v + P.pos[o];
    }
    gsync();

    for (int blk = 0; blk < NB; blk++) {
        // ---- LN1 (+fold prev fc2 partials+bias+residual), shift+window -> y ----
        {
            const float* fb = P.fc2_b + (blk - 1) * C;
            const float* w  = P.ln1_w + blk * C;
            const float* bv = P.ln1_b + blk * C;
            for (int hw = bid; hw < 256; hw += NCTA) {
                int h = hw >> 4, wd = hw & 15;
                int srcRow = (((h + 4) & 15) << 4) + ((wd + 4) & 15);
                int wi = ((h >> 3) << 1) + (wd >> 3);
                int pos = ((h & 7) << 3) + (wd & 7);
                int dstRow = wi * 64 + pos;
                float x0 = 0.f, x1 = 0.f, x2 = 0.f;
                if (tid < 128) {
                    float* tr = g_t + srcRow * C;
                    x0 = tr[tid]; x1 = tr[tid + 128]; x2 = tr[tid + 256];
                    if (blk > 0) {
                        float a0 = fb[tid], a1 = fb[tid + 128], a2 = fb[tid + 256];
#pragma unroll
                        for (int s = 0; s < 12; s++) {
                            const float* pq = g_part + (size_t)s * (L * C) + srcRow * C;
                            a0 += pq[tid]; a1 += pq[tid + 128]; a2 += pq[tid + 256];
                        }
                        x0 += a0; x1 += a1; x2 += a2;
                        tr[tid] = x0; tr[tid + 128] = x1; tr[tid + 256] = x2;
                    }
                }
                float s = x0 + x1 + x2;
#pragma unroll
                for (int o = 16; o; o >>= 1) s += __shfl_xor_sync(0xffffffffu, s, o);
                if (tid < 128 && (tid & 31) == 0) red[tid >> 5] = s;
                __syncthreads();
                float mean = (red[0] + red[1] + red[2] + red[3]) * (1.f / 384.f);
                float d0 = x0 - mean, d1 = x1 - mean, d2 = x2 - mean;
                float s2 = d0 * d0 + d1 * d1 + d2 * d2;
#pragma unroll
                for (int o = 16; o; o >>= 1) s2 += __shfl_xor_sync(0xffffffffu, s2, o);
                __syncthreads();
                if (tid < 128 && (tid & 31) == 0) red[tid >> 5] = s2;
                __syncthreads();
                float var = (red[0] + red[1] + red[2] + red[3]) * (1.f / 384.f);
                float rstd = rsqrtf(var + 1e-5f);
                if (tid < 128) {
                    float* dst = g_y + dstRow * C;
                    dst[tid]       = d0 * rstd * w[tid]       + bv[tid];
                    dst[tid + 128] = d1 * rstd * w[tid + 128] + bv[tid + 128];
                    dst[tid + 256] = d2 * rstd * w[tid + 256] + bv[tid + 256];
                }
                __syncthreads();
            }
        }
        gsync();

        // ---- qkv GEMM (M=256, N=1152, K=384, S=4, nt=3) ----
        if (bid < 288) {
            int s = bid & 3, tile = bid >> 2;       // tile 0..71
            int mt = tile & 3, ntl = tile >> 2;     // ntl 0..17
            gemm_core<0>(g_y, 384, P.qkv_w + (size_t)blk * 3 * C * C, 384, 0,
                         g_qkvp + (size_t)s * (L * 1152), 1152,
                         mt * 64, ntl * 64, s * 96, 3, sm);
        }
        gsync();

        // ---- attention (folds 4 qkv partials); idle CTAs prefetch weights ----
        if (bid < 48) {
            int wi = bid / NH, hd = bid % NH;
            float (*qs)[32] = (float(*)[32])sm;
            float (*ks)[32] = (float(*)[32])(sm + 8192);
            float (*vs)[32] = (float(*)[32])(sm + 16384);
            float (*ps)[68] = (float(*)[68])(sm + 24576);
            int row = tid >> 2, l4 = tid & 3;
            const float* p0 = g_qkvp + (size_t)(wi * 64 + row) * 1152 + hd * 32;
            int c0 = l4 * 8;
#pragma unroll
            for (int u = 0; u < 8; u += 4) {
                int cc = c0 + u;
                float4 aq = *(const float4*)(p0 + cc);
                float4 ak = *(const float4*)(p0 + 384 + cc);
                float4 av = *(const float4*)(p0 + 768 + cc);
#pragma unroll
                for (int pz = 1; pz < 4; pz++) {
                    const float* pp = p0 + (size_t)pz * (L * 1152);
                    float4 q2 = *(const float4*)(pp + cc);
                    float4 k2 = *(const float4*)(pp + 384 + cc);
                    float4 v2 = *(const float4*)(pp + 768 + cc);
                    aq.x += q2.x; aq.y += q2.y; aq.z += q2.z; aq.w += q2.w;
                    ak.x += k2.x; ak.y += k2.y; ak.z += k2.z; ak.w += k2.w;
                    av.x += v2.x; av.y += v2.y; av.z += v2.z; av.w += v2.w;
                }
                qs[row][cc] = aq.x; qs[row][cc + 1] = aq.y; qs[row][cc + 2] = aq.z; qs[row][cc + 3] = aq.w;
                ks[row][cc] = ak.x; ks[row][cc + 1] = ak.y; ks[row][cc + 2] = ak.z; ks[row][cc + 3] = ak.w;
                vs[row][cc] = av.x; vs[row][cc + 1] = av.y; vs[row][cc + 2] = av.z; vs[row][cc + 3] = av.w;
            }
            __syncthreads();
            float qreg[32];
#pragma unroll
            for (int d = 0; d < 32; d++) qreg[d] = qs[row][d];
            int yi = row >> 3, xi = row & 7;
            int ri = region3(((wi >> 1) << 3) + yi) * 3 + region3(((wi & 1) << 3) + xi);
            const float* rpb = P.rpb + (size_t)blk * 225 * NH;
            const float scale = 0.17677669529663687f;
            float sl[16];
            int j0 = l4 * 16;
            float mx = -1e30f;
#pragma unroll
            for (int jj = 0; jj < 16; jj++) {
                int j = j0 + jj;
                float acc = 0.f;
#pragma unroll
                for (int d = 0; d < 32; d++) acc += qreg[d] * ks[j][d];
                int yj = j >> 3, xj = j & 7;
                float bias = rpb[((yi - yj + 7) * 15 + (xi - xj + 7)) * NH + hd];
                int rj = region3(((wi >> 1) << 3) + yj) * 3 + region3(((wi & 1) << 3) + xj);
                sl[jj] = acc * scale + bias + ((ri == rj) ? 0.f : -100.f);
                mx = fmaxf(mx, sl[jj]);
            }
            mx = fmaxf(mx, __shfl_xor_sync(0xffffffffu, mx, 1));
            mx = fmaxf(mx, __shfl_xor_sync(0xffffffffu, mx, 2));
            float sum = 0.f;
#pragma unroll
            for (int jj = 0; jj < 16; jj++) { sl[jj] = expf(sl[jj] - mx); sum += sl[jj]; }
            sum += __shfl_xor_sync(0xffffffffu, sum, 1);
            sum += __shfl_xor_sync(0xffffffffu, sum, 2);
            float inv = 1.0f / sum;
#pragma unroll
            for (int jj = 0; jj < 16; jj++) ps[row][j0 + jj] = sl[jj];
            __syncwarp();
            int d0 = l4 * 8;
            float acc[8];
#pragma unroll
            for (int dd = 0; dd < 8; dd++) acc[dd] = 0.f;
            for (int j = 0; j < 64; j++) {
                float p = ps[row][j];
#pragma unroll
                for (int dd = 0; dd < 8; dd++) acc[dd] += p * vs[j][d0 + dd];
            }
            float* o = g_att + (size_t)(wi * 64 + row) * C + hd * 32 + d0;
#pragma unroll
            for (int dd = 0; dd < 8; dd++) o[dd] = acc[dd] * inv;
        } else {
            // prefetch proj_w, fc1_w, fc2_w for this block into L2
            int t = (bid - 48) * 256 + tid;
            const float* pw = P.proj_w + (size_t)blk * C * C;
            const float* w1 = P.fc1_w + (size_t)blk * MLPD * C;
            const float* w2 = P.fc2_w + (size_t)blk * C * MLPD;
            for (int i = t; i < C * C / 4; i += 248 * 256) l2pf(pw + i * 4);
            for (int i = t; i < MLPD * C / 4; i += 248 * 256) {
                l2pf(w1 + i * 4);
                l2pf(w2 + i * 4);
            }
        }
        gsync();

        // ---- proj GEMM (M=256, N=384, K=384, S=12, nt=1) ----
        if (bid < 288) {
            int s = bid % 12, tile = bid / 12;
            int mt = tile & 3, ntl = tile >> 2;
            gemm_core<0>(g_att, 384, P.proj_w + (size_t)blk * C * C, 384, 0,
                         g_part + (size_t)s * (L * C), C, mt * 64, ntl * 64, s * 32, 1, sm);
        }
        gsync();

        // ---- LN2 (+fold 12 proj partials w/ unshift + bias + residual) -> z ----
        {
            const float* pb = P.proj_b + blk * C;
            const float* w  = P.ln2_w + blk * C;
            const float* bv = P.ln2_b + blk * C;
            for (int r = bid; r < 256; r += NCTA) {
                int h = r >> 4, wd = r & 15;
                int hs = (h + 12) & 15, ws_ = (wd + 12) & 15;
                int wi = ((hs >> 3) << 1) + (ws_ >> 3);
                int pos = ((hs & 7) << 3) + (ws_ & 7);
                int mw = wi * 64 + pos;
                float x0 = 0.f, x1 = 0.f, x2 = 0.f;
                if (tid < 128) {
                    float* tr = g_t + r * C;
                    float a0 = pb[tid], a1 = pb[tid + 128], a2 = pb[tid + 256];
#pragma unroll
                    for (int s = 0; s < 12; s++) {
                        const float* pq = g_part + (size_t)s * (L * C) + mw * C;
                        a0 += pq[tid]; a1 += pq[tid + 128]; a2 += pq[tid + 256];
                    }
                    x0 = tr[tid] + a0; x1 = tr[tid + 128] + a1; x2 = tr[tid + 256] + a2;
                    tr[tid] = x0; tr[tid + 128] = x1; tr[tid + 256] = x2;
                }
                float s = x0 + x1 + x2;
#pragma unroll
                for (int o = 16; o; o >>= 1) s += __shfl_xor_sync(0xffffffffu, s, o);
                if (tid < 128 && (tid & 31) == 0) red[tid >> 5] = s;
                __syncthreads();
                float mean = (red[0] + red[1] + red[2] + red[3]) * (1.f / 384.f);
                float d0 = x0 - mean, d1 = x1 - mean, d2 = x2 - mean;
                float s2 = d0 * d0 + d1 * d1 + d2 * d2;
#pragma unroll
                for (int o = 16; o; o >>= 1) s2 += __shfl_xor_sync(0xffffffffu, s2, o);
                __syncthreads();
                if (tid < 128 && (tid & 31) == 0) red[tid >> 5] = s2;
                __syncthreads();
                float var = (red[0] + red[1] + red[2] + red[3]) * (1.f / 384.f);
                float rstd = rsqrtf(var + 1e-5f);
                if (tid < 128) {
                    float* dst = g_z + r * C;
                    dst[tid]       = d0 * rstd * w[tid]       + bv[tid];
                    dst[tid + 128] = d1 * rstd * w[tid + 128] + bv[tid + 128];
                    dst[tid + 256] = d2 * rstd * w[tid + 256] + bv[tid + 256];
                }
                __syncthreads();
            }
        }
        gsync();

        // ---- fc1 GEMM (M=256, N=1536, K=384, S=1) + bias + gelu -> h1 ----
        if (bid < 96) {
            int mt = bid & 3, ntl = bid >> 2;
            gemm_core<1>(g_z, 384, P.fc1_w + (size_t)blk * MLPD * C, 384,
                         P.fc1_b + (size_t)blk * MLPD,
                         g_h1, MLPD, mt * 64, ntl * 64, 0, 12, sm);
        } else {
            // prefetch next block's qkv weights (or dt1_w on last block)
            int t = (bid - 96) * 256 + tid;
            const float* nw = (blk + 1 < NB) ? P.qkv_w + (size_t)(blk + 1) * 3 * C * C
                                             : P.dt1_w;
            int n4 = (blk + 1 < NB) ? (3 * C * C / 4) : (294912 / 4);
            for (int i = t; i < n4; i += 200 * 256) l2pf(nw + i * 4);
        }
        gsync();

        // ---- fc2 GEMM (M=256, N=384, K=1536, S=12, nt=4) ----
        if (bid < 288) {
            int s = bid % 12, tile = bid / 12;
            int mt = tile & 3, ntl = tile >> 2;
            gemm_core<0>(g_h1, MLPD, P.fc2_w + (size_t)blk * C * MLPD, MLPD, 0,
                         g_part + (size_t)s * (L * C), C, mt * 64, ntl * 64, s * 128, 4, sm);
        }
        gsync();
    }

    // ---- fold last fc2 into t ----
    {
        const float* fb = P.fc2_b + 11 * C;
        for (int i = bid * 256 + tid; i < L * C; i += NCTA * 256) {
            int n = i % C;
            float v = fb[n];
#pragma unroll
            for (int s = 0; s < 12; s++) v += g_part[(size_t)s * (L * C) + i];
            g_t[i] += v;
        }
    }
    gsync();

    // ---- decoder: skip 1x1 conv + d1 deconv+BN+ReLU (192 CTAs) ----
    if (bid < 192) {
        int o = bid % 3, pg = bid / 3;          // pg 0..63, 4 patches each
        float (*ts)[384] = (float(*)[384])sm;
        for (int i = tid; i < 4 * 384; i += 256)
            ts[i / 384][i % 384] = g_t[(pg * 4 + i / 384) * C + (i % 384)];
        __syncthreads();
        float acc[4];
#pragma unroll
        for (int g = 0; g < 4; g++) acc[g] = P.dt1_b[o];
        for (int cc = 0; cc < C; cc++) {
            float wv = P.dt1_w[cc * 768 + o * 256 + tid];
#pragma unroll
            for (int g = 0; g < 4; g++) acc[g] += ts[g][cc] * wv;
        }
        float a = P.bn1_w[o] * INV_S, bbv = P.bn1_b[o];
        int k = tid >> 4, l = tid & 15;
#pragma unroll
        for (int g = 0; g < 4; g++) {
            int patch = pg * 4 + g;
            int h = patch >> 4, w = patch & 15;
            g_d1[o * 65536 + (h * 16 + k) * 256 + (w * 16 + l)] =
                fmaxf(0.f, acc[g] * a + bbv);
        }
    } else if (bid < 196) {
        int o = bid - 192;
        float acc = P.skip_b[o];
        for (int cc = 0; cc < C; cc++) acc += g_t[tid * C + cc] * P.skip_w[o * C + cc];
        g_skip[o * 256 + tid] = acc;
    }
    gsync();

    // ---- final output: deconv(3->4,k16,s16) + BN + bilinear skip + reshape ----
    {
        const float* w2 = P.dt2_w;
        for (int idx4 = bid * 256 + tid; idx4 < 16777216; idx4 += NCTA * 256) {
            int idx = idx4 << 2;
            int o = idx >> 24;
            int rem = idx & 0xFFFFFF;
            int Y = rem >> 12, X = rem & 4095;
            int H = Y >> 4, k = Y & 15, W = X >> 4;
            float d0 = g_d1[0 * 65536 + H * 256 + W];
            float d1v = g_d1[1 * 65536 + H * 256 + W];
            float d2 = g_d1[2 * 65536 + H * 256 + W];
            float bnwo = P.bn2_w[o] * INV_S, bnbo = P.bn2_b[o], b2o = P.dt2_b[o];
            int y0 = Y / 273;
            float fy = (float)(Y - y0 * 273) * (1.0f / 273.0f);
            int y1 = min(y0 + 1, 15);
            const float* sk = g_skip + o * 256;
            float r[4];
#pragma unroll
            for (int j = 0; j < 4; j++) {
                int Xj = X + j;
                int l = Xj & 15;
                int kl = k * 16 + l;
                float acc = b2o + d0 * w2[0 * 1024 + o * 256 + kl]
                                + d1v * w2[1 * 1024 + o * 256 + kl]
                                + d2 * w2[2 * 1024 + o * 256 + kl];
                acc = acc * bnwo + bnbo;
                int x0 = Xj / 273;
                float fx = (float)(Xj - x0 * 273) * (1.0f / 273.0f);
                int x1 = min(x0 + 1, 15);
                float v00 = sk[y0 * 16 + x0], v01 = sk[y0 * 16 + x1];
                float v10 = sk[y1 * 16 + x0], v11 = sk[y1 * 16 + x1];
                float vt = v00 + (v01 - v00) * fx;
                float vb = v10 + (v11 - v10) * fx;
                r[j] = acc + vt + (vb - vt) * fy;
            }
            P.out[idx4] = make_float4(r[0], r[1], r[2], r[3]);
        }
    }
}

// ---------------- host launch ----------------
extern "C" void kernel_launch(void* const* d_in, const int* in_sizes, int n_in,
                              void* d_out, int out_size)
{
    MegaParams P;
    P.x       = (const float*)d_in[0];
    P.patch_w = (const float*)d_in[1];
    P.patch_b = (const float*)d_in[2];
    P.pos     = (const float*)d_in[3];
    P.ln1_w   = (const float*)d_in[4];
    P.ln1_b   = (const float*)d_in[5];
    P.qkv_w   = (const float*)d_in[6];
    P.proj_w  = (const float*)d_in[7];
    P.proj_b  = (const float*)d_in[8];
    P.rpb     = (const float*)d_in[9];
    P.ln2_w   = (const float*)d_in[10];
    P.ln2_b   = (const float*)d_in[11];
    P.fc1_w   = (const float*)d_in[12];
    P.fc1_b   = (const float*)d_in[13];
    P.fc2_w   = (const float*)d_in[14];
    P.fc2_b   = (const float*)d_in[15];
    P.skip_w  = (const float*)d_in[16];
    P.skip_b  = (const float*)d_in[17];
    P.dt1_w   = (const float*)d_in[18];
    P.dt1_b   = (const float*)d_in[19];
    P.bn1_w   = (const float*)d_in[20];
    P.bn1_b   = (const float*)d_in[21];
    P.dt2_w   = (const float*)d_in[22];
    P.dt2_b   = (const float*)d_in[23];
    P.bn2_w   = (const float*)d_in[24];
    P.bn2_b   = (const float*)d_in[25];
    P.out     = (float4*)d_out;

    cudaFuncSetAttribute(mega, cudaFuncAttributeMaxDynamicSharedMemorySize, MEGA_SMEM);

    reset_kernel<<<1, 256>>>();
    mega<<<NCTA, 256, MEGA_SMEM>>>(P);
}

// round 13
// speedup vs baseline: 1.0572x; 1.0572x over previous
#include <cuda_runtime.h>
#include <math.h>

// ---------------- constants ----------------
#define L 256
#define C 384
#define NH 12
#define MLPD 1536
#define NB 12
#define NCTA 296
#define INV_S 0.99999500003749968f
#define GEMM_SMEM (4 * 64 * 36 * 4)
#define MEGA_SMEM (2 * GEMM_SMEM)

// ---------------- scratch ----------------
__device__ __align__(16) float g_t[L * C];
__device__ __align__(16) float g_y[L * C];
__device__ __align__(16) float g_att[L * C];
__device__ __align__(16) float g_z[L * C];
__device__ __align__(16) float g_h1[L * MLPD];
__device__ __align__(16) float g_qkvp[4 * L * 3 * C];   // qkv split-K partials (S=4)
__device__ __align__(16) float g_part[12 * L * C];      // patch + proj partials
__device__ __align__(16) float g_part2[12 * L * C];     // fc2 partials
__device__ __align__(16) float g_col[L * 768];
__device__ __align__(16) float g_d1[3 * 256 * 256];
__device__ __align__(16) float g_skip[4 * 256];

// ---------------- dependency counters (each entry on its own 128B line) ----
#define COFF_LN1Y 0
#define COFF_LN1T (4 * 32)
#define COFF_QKV  (8 * 32)      // 72 entries: mt*18+ntl
#define COFF_ATT  (80 * 32)     // 4
#define COFF_PROJ (84 * 32)     // 4
#define COFF_Z    (88 * 32)     // 4
#define COFF_FC1  (92 * 32)     // 96 entries: mt*24+ntl
#define COFF_FC2  (188 * 32)    // 4
#define CTOT      (192 * 32)
__device__ unsigned g_c[CTOT];

// ---------------- global barrier (flat atomic, one-hop publish) ----------
__device__ unsigned g_cnt;
__device__ volatile unsigned g_gen;

__global__ void reset_kernel() {
    for (int i = threadIdx.x; i < CTOT; i += 256) g_c[i] = 0;
    if (threadIdx.x == 0) { g_cnt = 0; g_gen = 0; }
    __threadfence();
}

__device__ __forceinline__ void gsync() {
    __syncthreads();
    if (threadIdx.x == 0) {
        __threadfence();
        unsigned gen = g_gen;
        if (atomicAdd(&g_cnt, 1u) == NCTA - 1) {
            g_cnt = 0;
            __threadfence();
            g_gen = gen + 1;
        } else {
            int spins = 0;
            while (g_gen == gen) { if (++spins > 64) __nanosleep(32); }
        }
        __threadfence();
    }
    __syncthreads();
}

// wait until monotonic counter reaches target (tid0 only)
__device__ __forceinline__ void wait_ge(int idx, unsigned tgt) {
    volatile unsigned* p = &g_c[idx];
    int spins = 0;
    while (*p < tgt) { if (++spins > 64) __nanosleep(32); }
}
__device__ __forceinline__ void post(int idx) {
    __threadfence();
    atomicAdd(&g_c[idx], 1u);
}

// ---------------- helpers ----------------
__device__ __forceinline__ void mma_tf32(float c[4], unsigned a0, unsigned a1,
                                         unsigned a2, unsigned a3,
                                         unsigned b0, unsigned b1)
{
    asm volatile(
        "mma.sync.aligned.m16n8k8.row.col.f32.tf32.tf32.f32 "
        "{%0,%1,%2,%3}, {%4,%5,%6,%7}, {%8,%9}, {%0,%1,%2,%3};"
        : "+f"(c[0]), "+f"(c[1]), "+f"(c[2]), "+f"(c[3])
        : "r"(a0), "r"(a1), "r"(a2), "r"(a3), "r"(b0), "r"(b1));
}
__device__ __forceinline__ float gelu_f(float s) {
    return 0.5f * s * (1.0f + erff(s * 0.70710678118654752f));
}
__device__ __forceinline__ void cp16(void* s, const void* g) {
    unsigned sa = (unsigned)__cvta_generic_to_shared(s);
    asm volatile("cp.async.cg.shared.global [%0], [%1], 16;" :: "r"(sa), "l"(g) : "memory");
}
__device__ __forceinline__ void l2pf(const void* g) {
    asm volatile("prefetch.global.L2 [%0];" :: "l"(g));
}
#define CP_COMMIT() asm volatile("cp.async.commit_group;" ::: "memory")
#define CP_WAIT2()  asm volatile("cp.async.wait_group 2;" ::: "memory")

__device__ __forceinline__ unsigned rnd_tf(float x) {
    return __float_as_uint(x) + 0x1000u;
}

// ---------------- TF32 GEMM, cp.async 4-stage pipeline ----------------
template<int EPI>
__device__ void gemm_core(const float* __restrict__ A, int lda,
                          const float* __restrict__ Bw, int ldb,
                          const float* __restrict__ bias,
                          float* __restrict__ outp, int N,
                          int bm, int bn, int k0, int nt, char* smbase)
{
    float (*As)[64][36] = (float(*)[64][36])smbase;
    float (*Bs)[64][36] = (float(*)[64][36])(smbase + GEMM_SMEM);
    const int tid = threadIdx.x;
    const int warp = tid >> 5, lane = tid & 31;
    const int wm = warp & 3, wn = warp >> 2;
    const int grp = lane >> 2, tig = lane & 3;
    const int lr = tid >> 2, lc = (tid & 3) * 8;

    float c[4][4];
#pragma unroll
    for (int i = 0; i < 4; i++)
#pragma unroll
        for (int j = 0; j < 4; j++) c[i][j] = 0.f;

    const float* Ap = A + (size_t)(bm + lr) * lda + k0 + lc;
    const float* Bp = Bw + (size_t)(bn + lr) * ldb + k0 + lc;

#pragma unroll
    for (int s = 0; s < 3; s++) {
        if (s < nt) {
            cp16(&As[s][lr][lc],     Ap + s * 32);
            cp16(&As[s][lr][lc + 4], Ap + s * 32 + 4);
            cp16(&Bs[s][lr][lc],     Bp + s * 32);
            cp16(&Bs[s][lr][lc + 4], Bp + s * 32 + 4);
        }
        CP_COMMIT();
    }

    for (int it = 0; it < nt; it++) {
        CP_WAIT2();
        __syncthreads();
        int buf = it & 3;
#pragma unroll
        for (int ks = 0; ks < 4; ks++) {
            int kk = ks * 8;
            unsigned a0 = rnd_tf(As[buf][wm * 16 + grp][kk + tig]);
            unsigned a1 = rnd_tf(As[buf][wm * 16 + grp + 8][kk + tig]);
            unsigned a2 = rnd_tf(As[buf][wm * 16 + grp][kk + tig + 4]);
            unsigned a3 = rnd_tf(As[buf][wm * 16 + grp + 8][kk + tig + 4]);
#pragma unroll
            for (int nb = 0; nb < 4; nb++) {
                unsigned b0 = rnd_tf(Bs[buf][wn * 32 + nb * 8 + grp][kk + tig]);
                unsigned b1 = rnd_tf(Bs[buf][wn * 32 + nb * 8 + grp][kk + tig + 4]);
                mma_tf32(c[nb], a0, a1, a2, a3, b0, b1);
            }
        }
        if (it + 3 < nt) {
            int nbuf = (it + 3) & 3;
            cp16(&As[nbuf][lr][lc],     Ap + (it + 3) * 32);
            cp16(&As[nbuf][lr][lc + 4], Ap + (it + 3) * 32 + 4);
            cp16(&Bs[nbuf][lr][lc],     Bp + (it + 3) * 32);
            cp16(&Bs[nbuf][lr][lc + 4], Bp + (it + 3) * 32 + 4);
        }
        CP_COMMIT();
    }

    int r0 = bm + wm * 16 + grp, r1 = r0 + 8;
#pragma unroll
    for (int nb = 0; nb < 4; nb++) {
        int col = bn + wn * 32 + nb * 8 + tig * 2;
        if (EPI == 0) {
            outp[(size_t)r0 * N + col]     = c[nb][0];
            outp[(size_t)r0 * N + col + 1] = c[nb][1];
            outp[(size_t)r1 * N + col]     = c[nb][2];
            outp[(size_t)r1 * N + col + 1] = c[nb][3];
        } else {
            float b0v = bias[col], b1v = bias[col + 1];
            outp[(size_t)r0 * N + col]     = gelu_f(c[nb][0] + b0v);
            outp[(size_t)r0 * N + col + 1] = gelu_f(c[nb][1] + b1v);
            outp[(size_t)r1 * N + col]     = gelu_f(c[nb][2] + b0v);
            outp[(size_t)r1 * N + col + 1] = gelu_f(c[nb][3] + b1v);
        }
    }
}

__device__ __forceinline__ int region3(int h) { return h < 8 ? 0 : (h < 12 ? 1 : 2); }

// ---------------- parameters ----------------
struct MegaParams {
    const float *x, *patch_w, *patch_b, *pos;
    const float *ln1_w, *ln1_b, *qkv_w, *proj_w, *proj_b, *rpb;
    const float *ln2_w, *ln2_b, *fc1_w, *fc1_b, *fc2_w, *fc2_b;
    const float *skip_w, *skip_b, *dt1_w, *dt1_b, *bn1_w, *bn1_b;
    const float *dt2_w, *dt2_b, *bn2_w, *bn2_b;
    float4* out;
};

// ---------------- the persistent megakernel (2 CTAs/SM, dataflow) --------
__global__ __launch_bounds__(256, 2) void mega(MegaParams P)
{
    extern __shared__ __align__(16) char sm[];
    __shared__ float red[4];
    const int bid = blockIdx.x;
    const int tid = threadIdx.x;

    // P0: im2col
    for (int i = bid * 256 + tid; i < 256 * 768; i += NCTA * 256) {
        int patch = i / 768, r = i % 768;
        int ch = r >> 8, pq = r & 255, pp = pq >> 4, q = pq & 15;
        int h = patch >> 4, w = patch & 15;
        g_col[i] = P.x[ch * 65536 + (h * 16 + pp) * 256 + (w * 16 + q)];
    }
    gsync();

    // P1: patch GEMM (S=12, nt=2) -> g_part
    if (bid < 288) {
        int s = bid % 12, tile = bid / 12;
        int mt = tile & 3, ntl = tile >> 2;
        gemm_core<0>(g_col, 768, P.patch_w, 768, 0,
                     g_part + (size_t)s * (L * C), C, mt * 64, ntl * 64, s * 64, 2, sm);
    } else {
        // prefetch ALL transformer weights into L2 (~fits; 86MB vs 126MB L2)
        int t = (bid - 288) * 256 + tid;
        for (int i = t; i < (3 * C * C * NB) / 4; i += 8 * 256) l2pf(P.qkv_w + i * 4);
        for (int i = t; i < (C * C * NB) / 4; i += 8 * 256) l2pf(P.proj_w + i * 4);
        for (int i = t; i < (MLPD * C * NB) / 4; i += 8 * 256) {
            l2pf(P.fc1_w + i * 4);
            l2pf(P.fc2_w + i * 4);
        }
    }
    gsync();

    // P2: patch reduce + bias + pos + buggy transpose
    for (int i = bid * 256 + tid; i < L * C; i += NCTA * 256) {
        int m = i / C, n = i % C;
        float v = P.patch_b[n];
#pragma unroll
        for (int s = 0; s < 12; s++) v += g_part[(size_t)s * (L * C) + i];
        int o = n * 256 + m;
        g_t[o] = v + P.pos[o];
    }
    gsync();

    for (int blk = 0; blk < NB; blk++) {
        unsigned ep = blk + 1;

        // ---- LN1: one row per CTA (bid<256); folds fc2 partials of prev block
        if (bid < 256) {
            int hw = bid;
            int h = hw >> 4, wd = hw & 15;
            int srcRow = (((h + 4) & 15) << 4) + ((wd + 4) & 15);
            int wi = ((h >> 3) << 1) + (wd >> 3);
            int pos = ((h & 7) << 3) + (wd & 7);
            int dstRow = wi * 64 + pos;
            if (tid == 0 && blk > 0) {
                wait_ge(COFF_FC2 + (srcRow >> 6) * 32, 72u * blk);
                __threadfence();
            }
            __syncthreads();
            const float* fb = P.fc2_b + (blk - 1) * C;
            const float* w  = P.ln1_w + blk * C;
            const float* bv = P.ln1_b + blk * C;
            float x0 = 0.f, x1 = 0.f, x2 = 0.f;
            if (tid < 128) {
                float* tr = g_t + srcRow * C;
                x0 = tr[tid]; x1 = tr[tid + 128]; x2 = tr[tid + 256];
                if (blk > 0) {
                    float a0 = fb[tid], a1 = fb[tid + 128], a2 = fb[tid + 256];
#pragma unroll
                    for (int s = 0; s < 12; s++) {
                        const float* pq = g_part2 + (size_t)s * (L * C) + srcRow * C;
                        a0 += pq[tid]; a1 += pq[tid + 128]; a2 += pq[tid + 256];
                    }
                    x0 += a0; x1 += a1; x2 += a2;
                    tr[tid] = x0; tr[tid + 128] = x1; tr[tid + 256] = x2;
                }
            }
            float s = x0 + x1 + x2;
#pragma unroll
            for (int o = 16; o; o >>= 1) s += __shfl_xor_sync(0xffffffffu, s, o);
            if (tid < 128 && (tid & 31) == 0) red[tid >> 5] = s;
            __syncthreads();
            float mean = (red[0] + red[1] + red[2] + red[3]) * (1.f / 384.f);
            float d0 = x0 - mean, d1 = x1 - mean, d2 = x2 - mean;
            float s2 = d0 * d0 + d1 * d1 + d2 * d2;
#pragma unroll
            for (int o = 16; o; o >>= 1) s2 += __shfl_xor_sync(0xffffffffu, s2, o);
            __syncthreads();
            if (tid < 128 && (tid & 31) == 0) red[tid >> 5] = s2;
            __syncthreads();
            float var = (red[0] + red[1] + red[2] + red[3]) * (1.f / 384.f);
            float rstd = rsqrtf(var + 1e-5f);
            if (tid < 128) {
                float* dst = g_y + dstRow * C;
                dst[tid]       = d0 * rstd * w[tid]       + bv[tid];
                dst[tid + 128] = d1 * rstd * w[tid + 128] + bv[tid + 128];
                dst[tid + 256] = d2 * rstd * w[tid + 256] + bv[tid + 256];
            }
            __syncthreads();
            if (tid == 0) {
                post(COFF_LN1Y + (dstRow >> 6) * 32);
                post(COFF_LN1T + (srcRow >> 6) * 32);
            }
        }

        // ---- qkv GEMM (S=4, nt=3) ----
        if (bid < 288) {
            int s = bid & 3, tile = bid >> 2;
            int mt = tile & 3, ntl = tile >> 2;
            if (tid == 0) { wait_ge(COFF_LN1Y + mt * 32, 64u * ep); __threadfence(); }
            __syncthreads();
            gemm_core<0>(g_y, 384, P.qkv_w + (size_t)blk * 3 * C * C, 384, 0,
                         g_qkvp + (size_t)s * (L * 1152), 1152,
                         mt * 64, ntl * 64, s * 96, 3, sm);
            __syncthreads();
            if (tid == 0) post(COFF_QKV + (mt * 18 + ntl) * 32);
        }

        // ---- attention (48 CTAs) ----
        if (bid < 48) {
            int wi = bid / NH, hd = bid % NH;
            if (tid == 0) {
                int hb = hd >> 1;
                wait_ge(COFF_QKV + (wi * 18 + hb) * 32, 4u * ep);
                wait_ge(COFF_QKV + (wi * 18 + 6 + hb) * 32, 4u * ep);
                wait_ge(COFF_QKV + (wi * 18 + 12 + hb) * 32, 4u * ep);
                __threadfence();
            }
            __syncthreads();
            float (*qs)[32] = (float(*)[32])sm;
            float (*ks)[32] = (float(*)[32])(sm + 8192);
            float (*vs)[32] = (float(*)[32])(sm + 16384);
            float (*ps)[68] = (float(*)[68])(sm + 24576);
            int row = tid >> 2, l4 = tid & 3;
            const float* p0 = g_qkvp + (size_t)(wi * 64 + row) * 1152 + hd * 32;
            int c0 = l4 * 8;
#pragma unroll
            for (int u = 0; u < 8; u += 4) {
                int cc = c0 + u;
                float4 aq = *(const float4*)(p0 + cc);
                float4 ak = *(const float4*)(p0 + 384 + cc);
                float4 av = *(const float4*)(p0 + 768 + cc);
#pragma unroll
                for (int pz = 1; pz < 4; pz++) {
                    const float* pp = p0 + (size_t)pz * (L * 1152);
                    float4 q2 = *(const float4*)(pp + cc);
                    float4 k2 = *(const float4*)(pp + 384 + cc);
                    float4 v2 = *(const float4*)(pp + 768 + cc);
                    aq.x += q2.x; aq.y += q2.y; aq.z += q2.z; aq.w += q2.w;
                    ak.x += k2.x; ak.y += k2.y; ak.z += k2.z; ak.w += k2.w;
                    av.x += v2.x; av.y += v2.y; av.z += v2.z; av.w += v2.w;
                }
                qs[row][cc] = aq.x; qs[row][cc + 1] = aq.y; qs[row][cc + 2] = aq.z; qs[row][cc + 3] = aq.w;
                ks[row][cc] = ak.x; ks[row][cc + 1] = ak.y; ks[row][cc + 2] = ak.z; ks[row][cc + 3] = ak.w;
                vs[row][cc] = av.x; vs[row][cc + 1] = av.y; vs[row][cc + 2] = av.z; vs[row][cc + 3] = av.w;
            }
            __syncthreads();
            float qreg[32];
#pragma unroll
            for (int d = 0; d < 32; d++) qreg[d] = qs[row][d];
            int yi = row >> 3, xi = row & 7;
            int ri = region3(((wi >> 1) << 3) + yi) * 3 + region3(((wi & 1) << 3) + xi);
            const float* rpb = P.rpb + (size_t)blk * 225 * NH;
            const float scale = 0.17677669529663687f;
            float sl[16];
            int j0 = l4 * 16;
            float mx = -1e30f;
#pragma unroll
            for (int jj = 0; jj < 16; jj++) {
                int j = j0 + jj;
                float acc = 0.f;
#pragma unroll
                for (int d = 0; d < 32; d++) acc += qreg[d] * ks[j][d];
                int yj = j >> 3, xj = j & 7;
                float bias = rpb[((yi - yj + 7) * 15 + (xi - xj + 7)) * NH + hd];
                int rj = region3(((wi >> 1) << 3) + yj) * 3 + region3(((wi & 1) << 3) + xj);
                sl[jj] = acc * scale + bias + ((ri == rj) ? 0.f : -100.f);
                mx = fmaxf(mx, sl[jj]);
            }
            mx = fmaxf(mx, __shfl_xor_sync(0xffffffffu, mx, 1));
            mx = fmaxf(mx, __shfl_xor_sync(0xffffffffu, mx, 2));
            float sum = 0.f;
#pragma unroll
            for (int jj = 0; jj < 16; jj++) { sl[jj] = expf(sl[jj] - mx); sum += sl[jj]; }
            sum += __shfl_xor_sync(0xffffffffu, sum, 1);
            sum += __shfl_xor_sync(0xffffffffu, sum, 2);
            float inv = 1.0f / sum;
#pragma unroll
            for (int jj = 0; jj < 16; jj++) ps[row][j0 + jj] = sl[jj];
            __syncwarp();
            int d0 = l4 * 8;
            float acc[8];
#pragma unroll
            for (int dd = 0; dd < 8; dd++) acc[dd] = 0.f;
            for (int j = 0; j < 64; j++) {
                float p = ps[row][j];
#pragma unroll
                for (int dd = 0; dd < 8; dd++) acc[dd] += p * vs[j][d0 + dd];
            }
            float* o = g_att + (size_t)(wi * 64 + row) * C + hd * 32 + d0;
#pragma unroll
            for (int dd = 0; dd < 8; dd++) o[dd] = acc[dd] * inv;
            __syncthreads();
            if (tid == 0) post(COFF_ATT + wi * 32);
        }

        // ---- proj GEMM (S=12, nt=1) -> g_part ----
        if (bid < 288) {
            int s = bid % 12, tile = bid / 12;
            int mt = tile & 3, ntl = tile >> 2;
            if (tid == 0) { wait_ge(COFF_ATT + mt * 32, 12u * ep); __threadfence(); }
            __syncthreads();
            gemm_core<0>(g_att, 384, P.proj_w + (size_t)blk * C * C, 384, 0,
                         g_part + (size_t)s * (L * C), C, mt * 64, ntl * 64, s * 32, 1, sm);
            __syncthreads();
            if (tid == 0) post(COFF_PROJ + mt * 32);
        }

        // ---- LN2: one row per CTA (bid<256) ----
        if (bid < 256) {
            int r = bid;
            int h = r >> 4, wd = r & 15;
            int hs = (h + 12) & 15, ws_ = (wd + 12) & 15;
            int wi = ((hs >> 3) << 1) + (ws_ >> 3);
            int pos = ((hs & 7) << 3) + (ws_ & 7);
            int mw = wi * 64 + pos;
            if (tid == 0) {
                wait_ge(COFF_LN1T + (r >> 6) * 32, 64u * ep);
                wait_ge(COFF_PROJ + (mw >> 6) * 32, 72u * ep);
                __threadfence();
            }
            __syncthreads();
            const float* pb = P.proj_b + blk * C;
            const float* w  = P.ln2_w + blk * C;
            const float* bv = P.ln2_b + blk * C;
            float x0 = 0.f, x1 = 0.f, x2 = 0.f;
            if (tid < 128) {
                float* tr = g_t + r * C;
                float a0 = pb[tid], a1 = pb[tid + 128], a2 = pb[tid + 256];
#pragma unroll
                for (int s = 0; s < 12; s++) {
                    const float* pq = g_part + (size_t)s * (L * C) + mw * C;
                    a0 += pq[tid]; a1 += pq[tid + 128]; a2 += pq[tid + 256];
                }
                x0 = tr[tid] + a0; x1 = tr[tid + 128] + a1; x2 = tr[tid + 256] + a2;
                tr[tid] = x0; tr[tid + 128] = x1; tr[tid + 256] = x2;
            }
            float s = x0 + x1 + x2;
#pragma unroll
            for (int o = 16; o; o >>= 1) s += __shfl_xor_sync(0xffffffffu, s, o);
            if (tid < 128 && (tid & 31) == 0) red[tid >> 5] = s;
            __syncthreads();
            float mean = (red[0] + red[1] + red[2] + red[3]) * (1.f / 384.f);
            float d0 = x0 - mean, d1 = x1 - mean, d2 = x2 - mean;
            float s2 = d0 * d0 + d1 * d1 + d2 * d2;
#pragma unroll
            for (int o = 16; o; o >>= 1) s2 += __shfl_xor_sync(0xffffffffu, s2, o);
            __syncthreads();
            if (tid < 128 && (tid & 31) == 0) red[tid >> 5] = s2;
            __syncthreads();
            float var = (red[0] + red[1] + red[2] + red[3]) * (1.f / 384.f);
            float rstd = rsqrtf(var + 1e-5f);
            if (tid < 128) {
                float* dst = g_z + r * C;
                dst[tid]       = d0 * rstd * w[tid]       + bv[tid];
                dst[tid + 128] = d1 * rstd * w[tid + 128] + bv[tid + 128];
                dst[tid + 256] = d2 * rstd * w[tid + 256] + bv[tid + 256];
            }
            __syncthreads();
            if (tid == 0) post(COFF_Z + (r >> 6) * 32);
        }

        // ---- fc1 GEMM (96 CTAs, nt=12) + bias + gelu -> h1 ----
        if (bid < 96) {
            int mt = bid & 3, ntl = bid >> 2;
            if (tid == 0) { wait_ge(COFF_Z + mt * 32, 64u * ep); __threadfence(); }
            __syncthreads();
            gemm_core<1>(g_z, 384, P.fc1_w + (size_t)blk * MLPD * C, 384,
                         P.fc1_b + (size_t)blk * MLPD,
                         g_h1, MLPD, mt * 64, ntl * 64, 0, 12, sm);
            __syncthreads();
            if (tid == 0) post(COFF_FC1 + (mt * 24 + ntl) * 32);
        }

        // ---- fc2 GEMM (S=12, nt=4) -> g_part2 ----
        if (bid < 288) {
            int s = bid % 12, tile = bid / 12;
            int mt = tile & 3, ntl = tile >> 2;
            if (tid == 0) {
                wait_ge(COFF_FC1 + (mt * 24 + 2 * s) * 32, ep);
                wait_ge(COFF_FC1 + (mt * 24 + 2 * s + 1) * 32, ep);
                __threadfence();
            }
            __syncthreads();
            gemm_core<0>(g_h1, MLPD, P.fc2_w + (size_t)blk * C * MLPD, MLPD, 0,
                         g_part2 + (size_t)s * (L * C), C, mt * 64, ntl * 64, s * 128, 4, sm);
            __syncthreads();
            if (tid == 0) post(COFF_FC2 + mt * 32);
        }
    }

    // ---- fold last fc2 into t (wait for all fc2 tiles of block 11) ----
    if (tid == 0) {
        wait_ge(COFF_FC2 + 0 * 32, 72u * NB);
        wait_ge(COFF_FC2 + 1 * 32, 72u * NB);
        wait_ge(COFF_FC2 + 2 * 32, 72u * NB);
        wait_ge(COFF_FC2 + 3 * 32, 72u * NB);
        __threadfence();
    }
    __syncthreads();
    {
        const float* fb = P.fc2_b + 11 * C;
        for (int i = bid * 256 + tid; i < L * C; i += NCTA * 256) {
            int n = i % C;
            float v = fb[n];
#pragma unroll
            for (int s = 0; s < 12; s++) v += g_part2[(size_t)s * (L * C) + i];
            g_t[i] += v;
        }
    }
    gsync();

    // ---- decoder: skip 1x1 conv + d1 deconv+BN+ReLU (192 CTAs) ----
    if (bid < 192) {
        int o = bid % 3, pg = bid / 3;
        float (*ts)[384] = (float(*)[384])sm;
        for (int i = tid; i < 4 * 384; i += 256)
            ts[i / 384][i % 384] = g_t[(pg * 4 + i / 384) * C + (i % 384)];
        __syncthreads();
        float acc[4];
#pragma unroll
        for (int g = 0; g < 4; g++) acc[g] = P.dt1_b[o];
        for (int cc = 0; cc < C; cc++) {
            float wv = P.dt1_w[cc * 768 + o * 256 + tid];
#pragma unroll
            for (int g = 0; g < 4; g++) acc[g] += ts[g][cc] * wv;
        }
        float a = P.bn1_w[o] * INV_S, bbv = P.bn1_b[o];
        int k = tid >> 4, l = tid & 15;
#pragma unroll
        for (int g = 0; g < 4; g++) {
            int patch = pg * 4 + g;
            int h = patch >> 4, w = patch & 15;
            g_d1[o * 65536 + (h * 16 + k) * 256 + (w * 16 + l)] =
                fmaxf(0.f, acc[g] * a + bbv);
        }
    } else if (bid < 196) {
        int o = bid - 192;
        float acc = P.skip_b[o];
        for (int cc = 0; cc < C; cc++) acc += g_t[tid * C + cc] * P.skip_w[o * C + cc];
        g_skip[o * 256 + tid] = acc;
    }
    gsync();

    // ---- final output ----
    {
        const float* w2 = P.dt2_w;
        for (int idx4 = bid * 256 + tid; idx4 < 16777216; idx4 += NCTA * 256) {
            int idx = idx4 << 2;
            int o = idx >> 24;
            int rem = idx & 0xFFFFFF;
            int Y = rem >> 12, X = rem & 4095;
            int H = Y >> 4, k = Y & 15, W = X >> 4;
            float d0 = g_d1[0 * 65536 + H * 256 + W];
            float d1v = g_d1[1 * 65536 + H * 256 + W];
            float d2 = g_d1[2 * 65536 + H * 256 + W];
            float bnwo = P.bn2_w[o] * INV_S, bnbo = P.bn2_b[o], b2o = P.dt2_b[o];
            int y0 = Y / 273;
            float fy = (float)(Y - y0 * 273) * (1.0f / 273.0f);
            int y1 = min(y0 + 1, 15);
            const float* sk = g_skip + o * 256;
            float r[4];
#pragma unroll
            for (int j = 0; j < 4; j++) {
                int Xj = X + j;
                int l = Xj & 15;
                int kl = k * 16 + l;
                float acc = b2o + d0 * w2[0 * 1024 + o * 256 + kl]
                                + d1v * w2[1 * 1024 + o * 256 + kl]
                                + d2 * w2[2 * 1024 + o * 256 + kl];
                acc = acc * bnwo + bnbo;
                int x0 = Xj / 273;
                float fx = (float)(Xj - x0 * 273) * (1.0f / 273.0f);
                int x1 = min(x0 + 1, 15);
                float v00 = sk[y0 * 16 + x0], v01 = sk[y0 * 16 + x1];
                float v10 = sk[y1 * 16 + x0], v11 = sk[y1 * 16 + x1];
                float vt = v00 + (v01 - v00) * fx;
                float vb = v10 + (v11 - v10) * fx;
                r[j] = acc + vt + (vb - vt) * fy;
            }
            P.out[idx4] = make_float4(r[0], r[1], r[2], r[3]);
        }
    }
}

// ---------------- host launch ----------------
extern "C" void kernel_launch(void* const* d_in, const int* in_sizes, int n_in,
                              void* d_out, int out_size)
{
    MegaParams P;
    P.x       = (const float*)d_in[0];
    P.patch_w = (const float*)d_in[1];
    P.patch_b = (const float*)d_in[2];
    P.pos     = (const float*)d_in[3];
    P.ln1_w   = (const float*)d_in[4];
    P.ln1_b   = (const float*)d_in[5];
    P.qkv_w   = (const float*)d_in[6];
    P.proj_w  = (const float*)d_in[7];
    P.proj_b  = (const float*)d_in[8];
    P.rpb     = (const float*)d_in[9];
    P.ln2_w   = (const float*)d_in[10];
    P.ln2_b   = (const float*)d_in[11];
    P.fc1_w   = (const float*)d_in[12];
    P.fc1_b   = (const float*)d_in[13];
    P.fc2_w   = (const float*)d_in[14];
    P.fc2_b   = (const float*)d_in[15];
    P.skip_w  = (const float*)d_in[16];
    P.skip_b  = (const float*)d_in[17];
    P.dt1_w   = (const float*)d_in[18];
    P.dt1_b   = (const float*)d_in[19];
    P.bn1_w   = (const float*)d_in[20];
    P.bn1_b   = (const float*)d_in[21];
    P.dt2_w   = (const float*)d_in[22];
    P.dt2_b   = (const float*)d_in[23];
    P.bn2_w   = (const float*)d_in[24];
    P.bn2_b   = (const float*)d_in[25];
    P.out     = (float4*)d_out;

    cudaFuncSetAttribute(mega, cudaFuncAttributeMaxDynamicSharedMemorySize, MEGA_SMEM);

    reset_kernel<<<1, 256>>>();
    mega<<<NCTA, 256, MEGA_SMEM>>>(P);
}